// round 7
// baseline (speedup 1.0000x reference)
#include <cuda_runtime.h>
#include <cuda_bf16.h>
#include <cstdint>

// x (12,64,256,256) f32, w (64,64,3,3) f32, out (12,64,256,256) f32
// channel-shift (roll 32 over T*C=192) -> sign -> 3x3 same-pad conv, weights sign(w)*mean|w|[o]
// GEMM: M=128 px/CTA, N=64, K=576 via int8 mma.sync m16n8k32 (exact: partial sums <= 576)

__device__ float g_scale[64];
__device__ uint2 g_Bpack[9 * 2 * 8 * 32];   // [tap][kt(2)][nt(8)][lane] -> (b0,b1), 36864 B

// smem: B 36864 | A tile 13056 (102 rows * 128B, pixel-pairs swizzled) | scale 256
#define SM_A_OFF   36864
#define SM_SC_OFF  49920
#define SMEM_DYN   50176

__device__ __forceinline__ uint32_t sign_s8(float x) {     // byte value: +1, 0xFF(-1), 0
    uint32_t u = __float_as_uint(x);
    uint32_t mag = u & 0x7FFFFFFFu;
    return mag ? ((u >> 31) ? 0xFFu : 0x01u) : 0u;
}

// -------------------- weight prep --------------------

__global__ void prep_scale_kernel(const float* __restrict__ w) {
    int o = blockIdx.x, tid = threadIdx.x;
    float s = 0.f;
    for (int i = tid; i < 576; i += 256) s += fabsf(w[o * 576 + i]);
    #pragma unroll
    for (int off = 16; off; off >>= 1) s += __shfl_down_sync(0xFFFFFFFFu, s, off);
    __shared__ float red[8];
    if ((tid & 31) == 0) red[tid >> 5] = s;
    __syncthreads();
    if (tid < 8) {
        float v = red[tid];
        #pragma unroll
        for (int off = 4; off; off >>= 1) v += __shfl_down_sync(0xFFu, v, off);
        if (tid == 0) g_scale[o] = v * (1.0f / 576.0f);
    }
}

// Pack sign(w) into the m16n8k32 s8 B-fragment layout:
// lane (tig=lane&3, g=lane>>2), col n = g (out-ch o = nt*8+g);
// b0 bytes j=0..3: k = 4*tig+j  -> channel kt*32 + 4*tig + j
// b1 bytes j=0..3: k = 16+4*tig+j -> channel kt*32 + 16 + 4*tig + j
__global__ void prep_B_kernel(const float* __restrict__ w) {
    int tap = blockIdx.x;            // 0..8
    int kt  = blockIdx.y;            // 0..1
    int tid = threadIdx.x;           // 256
    int nt = tid >> 5, lane = tid & 31;
    int tig = lane & 3, g = lane >> 2;
    int o = nt * 8 + g;
    uint32_t b0 = 0, b1 = 0;
    #pragma unroll
    for (int j = 0; j < 4; j++) {
        int c0 = kt * 32 + 4 * tig + j;
        int c1 = c0 + 16;
        b0 |= (sign_s8(w[(o * 64 + c0) * 9 + tap]) & 0xFFu) << (8 * j);
        b1 |= (sign_s8(w[(o * 64 + c1) * 9 + tap]) & 0xFFu) << (8 * j);
    }
    g_Bpack[((tap * 2 + kt) * 8 + nt) * 32 + lane] = make_uint2(b0, b1);
}

// -------------------- fused shift+sign+conv --------------------
// A tile: 6x34 = 204 halo pixels, 64 s8 channels each. Pixel-pair rows of 128B:
// phys(p, off) = (p>>1)*128 + ((( (p&1)*64 + off )) ^ (((p>>1)&7)<<4)) at 16B granularity.

__global__ void __launch_bounds__(256, 2)
conv_kernel(const float* __restrict__ x, float* __restrict__ out) {
    extern __shared__ unsigned char smem[];
    uint2* sB = reinterpret_cast<uint2*>(smem);
    unsigned char* sA = smem + SM_A_OFF;
    float* sScale = reinterpret_cast<float*>(smem + SM_SC_OFF);

    const int tid = threadIdx.x;
    const int bt = blockIdx.z;                 // 0..11
    const int h0 = blockIdx.y * 4;
    const int w0 = blockIdx.x * 32;
    const int b = bt / 3, t = bt % 3;

    // stage packed B (2304 uint4) + scales
    {
        const uint4* src = reinterpret_cast<const uint4*>(g_Bpack);
        uint4* dst = reinterpret_cast<uint4*>(sB);
        #pragma unroll
        for (int k = 0; k < 9; k++) dst[tid + k * 256] = src[tid + k * 256];
    }
    if (tid < 64) sScale[tid] = g_scale[tid];

    // load A tile: 408 half-pixel tasks (pixel, 32-channel half), 2 per thread
    #pragma unroll
    for (int rep = 0; rep < 2; rep++) {
        int task = tid + rep * 256;
        if (task >= 408) break;
        int half = (task >= 204) ? 1 : 0;
        int pix = task - half * 204;
        int pr = pix / 34, pc = pix - pr * 34;
        int h = h0 - 1 + pr, ww = w0 - 1 + pc;
        bool valid = ((unsigned)h < 256u) && ((unsigned)ww < 256u);
        int sb = t * 64 + half * 32 - 32; if (sb < 0) sb += 192;   // channel-shift source base
        const float* xb = x + (long)(b * 192 + sb) * 65536 + h * 256 + ww;
        uint32_t wd[8];
        #pragma unroll
        for (int q = 0; q < 8; q++) {
            uint32_t v = 0;
            #pragma unroll
            for (int j = 0; j < 4; j++) {
                uint32_t s = valid ? sign_s8(__ldg(xb + ((long)(4 * q + j) << 16))) : 0u;
                v |= (s & 0xFFu) << (8 * j);
            }
            wd[q] = v;
        }
        int row = pix >> 1;
        uint32_t sw = ((uint32_t)row & 7u) << 4;
        uint32_t off0 = (uint32_t)((pix & 1) * 64 + half * 32);
        *reinterpret_cast<uint4*>(sA + row * 128 + ((off0      ) ^ sw)) = make_uint4(wd[0], wd[1], wd[2], wd[3]);
        *reinterpret_cast<uint4*>(sA + row * 128 + ((off0 + 16u) ^ sw)) = make_uint4(wd[4], wd[5], wd[6], wd[7]);
    }
    __syncthreads();

    // mainloop: 9 taps x 2 k-tiles; per warp: ldmatrix.x4 (A) + 8 x (LDS.64 B + IMMA)
    const int warp = tid >> 5, lane = tid & 31;
    const int ph  = warp >> 1;               // output tile row 0..3
    const int pw0 = (warp & 1) * 16;         // output tile col base 0/16
    const int tig = lane & 3, g = lane >> 2;

    int acc[8][4];
    #pragma unroll
    for (int nt = 0; nt < 8; nt++) { acc[nt][0] = acc[nt][1] = acc[nt][2] = acc[nt][3] = 0; }

    const uint32_t sA_base = (uint32_t)__cvta_generic_to_shared(sA);
    const int mrow = lane & 15;              // pixel row within m16
    const int h16  = lane >> 4;              // 16B chunk select (matrices 0/1 vs 2/3)

    #pragma unroll
    for (int tap = 0; tap < 9; tap++) {
        const int kh = tap / 3, kw = tap - kh * 3;
        const int p = (ph + kh) * 34 + pw0 + kw + mrow;     // this lane's pixel
        const int row = p >> 1;
        const uint32_t sw = ((uint32_t)row & 7u) << 4;
        const uint32_t offp = (uint32_t)((p & 1) * 64 + h16 * 16);
        #pragma unroll
        for (int kt = 0; kt < 2; kt++) {
            uint32_t a0, a1, a2, a3;
            uint32_t addr = sA_base + (uint32_t)row * 128u + ((offp + (uint32_t)(kt * 32)) ^ sw);
            asm volatile("ldmatrix.sync.aligned.x4.m8n8.shared.b16 {%0,%1,%2,%3}, [%4];"
                         : "=r"(a0), "=r"(a1), "=r"(a2), "=r"(a3) : "r"(addr));
            #pragma unroll
            for (int nt = 0; nt < 8; nt++) {
                uint2 bb = sB[((tap * 2 + kt) * 8 + nt) * 32 + lane];
                asm volatile(
                    "mma.sync.aligned.m16n8k32.row.col.s32.s8.s8.s32 "
                    "{%0,%1,%2,%3}, {%4,%5,%6,%7}, {%8,%9}, {%0,%1,%2,%3};"
                    : "+r"(acc[nt][0]), "+r"(acc[nt][1]), "+r"(acc[nt][2]), "+r"(acc[nt][3])
                    : "r"(a0), "r"(a1), "r"(a2), "r"(a3), "r"(bb.x), "r"(bb.y));
            }
        }
    }

    // epilogue: D(m,n): d0=(g,2tig) d1=(g,2tig+1) d2=(g+8,2tig) d3=(g+8,2tig+1)
    const int hh = h0 + ph;
    const int wb = w0 + pw0 + g;
    #pragma unroll
    for (int nt = 0; nt < 8; nt++) {
        int o0 = nt * 8 + 2 * tig;
        float s0 = sScale[o0], s1 = sScale[o0 + 1];
        long base0 = ((long)(bt * 64 + o0) << 16) + (hh << 8) + wb;
        long base1 = base0 + 65536;
        out[base0]     = s0 * (float)acc[nt][0];
        out[base1]     = s1 * (float)acc[nt][1];
        out[base0 + 8] = s0 * (float)acc[nt][2];
        out[base1 + 8] = s1 * (float)acc[nt][3];
    }
}

// -------------------- launch --------------------

extern "C" void kernel_launch(void* const* d_in, const int* in_sizes, int n_in,
                              void* d_out, int out_size) {
    const float* x = (const float*)d_in[0];
    const float* w = (const float*)d_in[1];
    float* out = (float*)d_out;

    cudaFuncSetAttribute(conv_kernel, cudaFuncAttributeMaxDynamicSharedMemorySize, SMEM_DYN);

    prep_scale_kernel<<<64, 256>>>(w);
    prep_B_kernel<<<dim3(9, 2, 1), 256>>>(w);
    conv_kernel<<<dim3(8, 64, 12), 256, SMEM_DYN>>>(x, out);
}